// round 12
// baseline (speedup 1.0000x reference)
#include <cuda_runtime.h>
#include <cuda_bf16.h>
#include <math.h>
#include <stdint.h>

// Shapes fixed by the dataset
#define H    512
#define Bm   64
#define T    256
#define BH   (Bm * H)
#define NBLK 128          // persistent blocks, 1/SM
#define NTHR 256

// ---- SMEM byte offsets ----
// Bfrag: weight fragments [layer2][pass2][ks64][nt2][lane32][reg2] b32 = 128KB
#define OFF_BF   0
// Afrag/Cp/Hs shared scratch, 32KB:
//   Afrag [pass2][ks8][mt4][r4][slot32] b32   (LSTM staging, per 128-K chunk)
//   Cp    [w8][b64][n16] f32                  (cross-warp reduction)
//   Hs    [b64][k128] f32                     (bayes activation chunk)
#define OFF_ACT  131072
#define OFF_MU   163840      // [4][512] f32 bayes mu rows (8KB)
#define OFF_SIG  172032      // (8KB)
#define OFF_WB   180224      // (8KB)
#define OFF_BS0  188416      // [16] f32
#define OFF_BS1  188480
#define OFF_BMU  188544
#define OFF_BSG  188560
#define OFF_BB   188576
#define SMEM_BYTES 188672

// ---- persistent device state (no allocations allowed) ----
__device__ unsigned g_bar;
__device__ volatile unsigned g_dead;   // watchdog
__device__ __align__(16) __nv_bfloat16 g_xhi[BH], g_xlo[BH];       // bayes out
__device__ __align__(16) __nv_bfloat16 g_h0hi[2][BH], g_h0lo[2][BH];
__device__ __align__(16) __nv_bfloat16 g_h1hi[2][BH], g_h1lo[2][BH];

// m16n8k16 bf16 mma, fp32 accumulate (sm_80+ baseline — OK on plain sm_100)
#define MMA16816(c, a, b)                                                        \
    asm volatile("mma.sync.aligned.m16n8k16.row.col.f32.bf16.bf16.f32 "          \
        "{%0,%1,%2,%3}, {%4,%5,%6,%7}, {%8,%9}, {%0,%1,%2,%3};"                  \
        : "+f"((c)[0]), "+f"((c)[1]), "+f"((c)[2]), "+f"((c)[3])                 \
        : "r"((a)[0]), "r"((a)[1]), "r"((a)[2]), "r"((a)[3]),                    \
          "r"((b)[0]), "r"((b)[1]))

// Packed fp32x2 ops for the bayes phase
#define FMA2(d, a, b) asm("fma.rn.f32x2 %0, %1, %2, %0;" : "+l"(d) : "l"(a), "l"(b))
#define ADD2(d, a)    asm("add.rn.f32x2 %0, %0, %1;"     : "+l"(d) : "l"(a))
__device__ __forceinline__ void unpack2(unsigned long long v, float& lo, float& hi) {
    asm("mov.b64 {%0, %1}, %2;" : "=f"(lo), "=f"(hi) : "l"(v));
}

__global__ void reset_kernel() { g_bar = 0u; g_dead = 0u; }

// Bounded grid barrier. Tight L2 polling (no nanosleep — wake-up latency was
// the suspected shared ~us/barrier cost); watchdog converts any wedge into
// fast termination instead of a container-killing hang.
__device__ __forceinline__ void grid_bar(unsigned target) {
    __syncthreads();
    if (threadIdx.x == 0) {
        __threadfence();
        atomicAdd(&g_bar, 1u);
        unsigned spin = 0;
        while (!g_dead) {
            unsigned v;
            asm volatile("ld.global.cg.u32 %0, [%1];" : "=r"(v) : "l"(&g_bar));
            if (v >= target) break;
            if (++spin > 100000000u) { g_dead = 1u; break; }
        }
        __threadfence();
    }
    __syncthreads();
}

__device__ __forceinline__ void split_store(float v, __nv_bfloat16* hi, __nv_bfloat16* lo) {
    __nv_bfloat16 h = __float2bfloat16(v);
    *hi = h;
    *lo = __float2bfloat16(v - __bfloat162float(h));
}

// ---- one LSTM layer phase via mma.sync ----
// gates C[64 batch][16 gatecols] = [xin | hprev] @ W^T, K=1024 in 8 chunks of 128.
// Warp w owns kstep w (16 K) of each chunk. 3-pass bf16 hi/lo split.
// Afrag slots XOR-swizzled by ks so staging STS hits the 4-cycle floor.
// Global loads double-buffered in registers.
__device__ __forceinline__ void lstm_phase_mma(
    char* smem, int layer,
    const __nv_bfloat16* __restrict__ xin_hi, const __nv_bfloat16* __restrict__ xin_lo,
    const __nv_bfloat16* __restrict__ hp_hi,  const __nv_bfloat16* __restrict__ hp_lo,
    const float* __restrict__ bsum, float& cr,
    __nv_bfloat16* __restrict__ hn_hi, __nv_bfloat16* __restrict__ hn_lo,
    float* __restrict__ out_t, int u0)
{
    const int tid  = threadIdx.x;
    const int w    = tid >> 5;      // warp id = kstep within chunk
    const int lane = tid & 31;
    uint32_t* af = (uint32_t*)(smem + OFF_ACT);
    const uint32_t* bfb = (const uint32_t*)(smem + OFF_BF);

    float acc[4][2][4];
    #pragma unroll
    for (int mt = 0; mt < 4; mt++)
        #pragma unroll
        for (int nt = 0; nt < 2; nt++)
            #pragma unroll
            for (int r = 0; r < 4; r++) acc[mt][nt][r] = 0.0f;

    // prefetch chunk 0 (always within xin)
    uint4 pr0[4], pr1[4];
    #pragma unroll
    for (int i = 0; i < 4; i++) {
        int job = tid + i * NTHR, pass = job >> 9, rem = job & 511;
        int b = rem >> 3, ks = rem & 7;
        const __nv_bfloat16* s = pass ? xin_lo : xin_hi;
        const __nv_bfloat16* p = s + (size_t)b * H + ks * 16;
        pr0[i] = __ldcg((const uint4*)p);
        pr1[i] = __ldcg((const uint4*)(p + 8));
    }

    for (int ck = 0; ck < 8; ck++) {
        __syncthreads();      // previous chunk's fragments fully consumed
        // ---- store prefetched chunk into fragment order (XOR slot swizzle) ----
        #pragma unroll
        for (int i = 0; i < 4; i++) {
            int job = tid + i * NTHR, pass = job >> 9, rem = job & 511;
            int b = rem >> 3, ks = rem & 7;
            int mt = b >> 4, g = b & 7, rb = (b >> 3) & 1;
            uint32_t base = ((uint32_t)(pass * 8 + ks) * 4 + mt) * 128
                          + (uint32_t)(((g ^ ks) & 7) * 4);
            *(uint4*)(af + base + rb * 32)       = pr0[i];   // k-lo plane
            *(uint4*)(af + base + (rb + 2) * 32) = pr1[i];   // k-hi plane
        }
        __syncthreads();
        // ---- prefetch next chunk (LDG latency overlaps compute below) ----
        if (ck + 1 < 8) {
            const int koff = (ck + 1) * 128 - ((ck + 1 >= 4) ? H : 0);
            const __nv_bfloat16* shi = (ck + 1 < 4) ? xin_hi : hp_hi;
            const __nv_bfloat16* slo = (ck + 1 < 4) ? xin_lo : hp_lo;
            #pragma unroll
            for (int i = 0; i < 4; i++) {
                int job = tid + i * NTHR, pass = job >> 9, rem = job & 511;
                int b = rem >> 3, ks = rem & 7;
                const __nv_bfloat16* s = pass ? slo : shi;
                const __nv_bfloat16* p = s + (size_t)b * H + koff + ks * 16;
                pr0[i] = __ldcg((const uint4*)p);
                pr1[i] = __ldcg((const uint4*)(p + 8));
            }
        }
        // ---- compute: warp w does kstep w of this chunk ----
        const int ksg = ck * 8 + w;            // global kstep 0..63
        const int sl = ((((lane >> 2) ^ w) & 7) * 4) + (lane & 3);
        uint32_t Ah[4][4], Al[4][4];
        #pragma unroll
        for (int mt = 0; mt < 4; mt++) {
            uint32_t bh = ((uint32_t)(0 * 8 + w) * 4 + mt) * 128 + sl;
            uint32_t bl = ((uint32_t)(1 * 8 + w) * 4 + mt) * 128 + sl;
            #pragma unroll
            for (int r = 0; r < 4; r++) {
                Ah[mt][r] = af[bh + r * 32];
                Al[mt][r] = af[bl + r * 32];
            }
        }
        uint32_t Bh[2][2], Bl[2][2];
        #pragma unroll
        for (int nt = 0; nt < 2; nt++) {
            uint32_t ih = ((((uint32_t)(layer * 2 + 0) * 64 + ksg) * 2 + nt) * 32 + lane) * 2;
            uint32_t il = ((((uint32_t)(layer * 2 + 1) * 64 + ksg) * 2 + nt) * 32 + lane) * 2;
            uint2 vh = *(const uint2*)(bfb + ih);
            uint2 vl = *(const uint2*)(bfb + il);
            Bh[nt][0] = vh.x; Bh[nt][1] = vh.y;
            Bl[nt][0] = vl.x; Bl[nt][1] = vl.y;
        }
        #pragma unroll
        for (int mt = 0; mt < 4; mt++)
            #pragma unroll
            for (int nt = 0; nt < 2; nt++) {
                MMA16816(acc[mt][nt], Ah[mt], Bh[nt]);
                MMA16816(acc[mt][nt], Ah[mt], Bl[nt]);
                MMA16816(acc[mt][nt], Al[mt], Bh[nt]);
            }
    }

    // ---- cross-warp K reduction via SMEM partials (reuses Afrag area) ----
    __syncthreads();                       // all fragment reads done
    float* cp = (float*)(smem + OFF_ACT);  // Cp[w][64][16]
    {
        int g = lane >> 2, tg = lane & 3;
        #pragma unroll
        for (int mt = 0; mt < 4; mt++)
            #pragma unroll
            for (int nt = 0; nt < 2; nt++) {
                int n0 = nt * 8 + tg * 2;
                int row = w * 64 + mt * 16 + g;
                *(float2*)(cp + row * 16 + n0) =
                    make_float2(acc[mt][nt][0], acc[mt][nt][1]);
                *(float2*)(cp + (row + 8) * 16 + n0) =
                    make_float2(acc[mt][nt][2], acc[mt][nt][3]);
            }
    }
    __syncthreads();

    // ---- cell update: thread -> (batch, unit); c in register all sequence ----
    {
        int b = tid >> 2, uu = tid & 3;
        float gsum[4];
        #pragma unroll
        for (int gate = 0; gate < 4; gate++) {
            int n = gate * 4 + uu;
            float s = 0.0f;
            #pragma unroll
            for (int ww = 0; ww < 8; ww++) s += cp[(ww * 64 + b) * 16 + n];
            gsum[gate] = s + bsum[n];
        }
        float iv = 1.0f / (1.0f + expf(-gsum[0]));
        float fv = 1.0f / (1.0f + expf(-gsum[1]));
        float gv = tanhf(gsum[2]);
        float ov = 1.0f / (1.0f + expf(-gsum[3]));
        float cn = fv * cr + iv * gv;
        cr = cn;
        float hn = ov * tanhf(cn);
        int idx = b * H + u0 + uu;
        split_store(hn, hn_hi + idx, hn_lo + idx);
        if (out_t) out_t[idx] = hn;
    }
}

extern "C" __global__ void __launch_bounds__(NTHR, 1)
dlstm_persistent(const float* __restrict__ init_h, const float* __restrict__ init_c,
                 const float* __restrict__ eps_w,  const float* __restrict__ eps_b,
                 const float* __restrict__ W_ih0, const float* __restrict__ W_hh0,
                 const float* __restrict__ b_ih0, const float* __restrict__ b_hh0,
                 const float* __restrict__ W_ih1, const float* __restrict__ W_hh1,
                 const float* __restrict__ b_ih1, const float* __restrict__ b_hh1,
                 const float* __restrict__ w_mu,  const float* __restrict__ w_lv,
                 const float* __restrict__ b_mu,  const float* __restrict__ b_lv,
                 float* __restrict__ out)
{
    extern __shared__ __align__(16) char smem[];
    const int tid = threadIdx.x;
    const int u0 = blockIdx.x * 4, j0 = u0;

    uint32_t* bfb  = (uint32_t*)(smem + OFF_BF);
    float* mu_s  = (float*)(smem + OFF_MU);
    float* sig_s = (float*)(smem + OFF_SIG);
    float* Wb    = (float*)(smem + OFF_WB);
    float* bsum0 = (float*)(smem + OFF_BS0);
    float* bsum1 = (float*)(smem + OFF_BS1);
    float* bmu_s = (float*)(smem + OFF_BMU);
    float* bsg_s = (float*)(smem + OFF_BSG);
    float* bb    = (float*)(smem + OFF_BB);
    float* Hs    = (float*)(smem + OFF_ACT);

    // ---- prologue: weight fragments (resident whole run) ----
    // idx = (layer, c 0..15, kq 0..511); B[k][n=c] = Wcat[row(c)][k], pairs (k,k+1).
    for (int idx = tid; idx < 2 * 16 * 512; idx += NTHR) {
        int l  = idx >> 13;
        int c  = (idx >> 9) & 15;
        int kq = idx & 511;
        int k  = kq * 2;
        int r  = (c >> 2) * H + u0 + (c & 3);
        const float* Wih = l ? W_ih1 : W_ih0;
        const float* Whh = l ? W_hh1 : W_hh0;
        const float* src = (k < H) ? (Wih + (size_t)r * H + k)
                                   : (Whh + (size_t)r * H + (k - H));
        float2 wv = *(const float2*)src;
        __nv_bfloat16 h0 = __float2bfloat16(wv.x);
        __nv_bfloat16 h1 = __float2bfloat16(wv.y);
        __nv_bfloat16 l0 = __float2bfloat16(wv.x - __bfloat162float(h0));
        __nv_bfloat16 l1 = __float2bfloat16(wv.y - __bfloat162float(h1));
        uint32_t hip, lop;
        asm("mov.b32 %0, {%1, %2};" : "=r"(hip) : "h"((unsigned short)__bfloat16_as_ushort(h0)),
                                                  "h"((unsigned short)__bfloat16_as_ushort(h1)));
        asm("mov.b32 %0, {%1, %2};" : "=r"(lop) : "h"((unsigned short)__bfloat16_as_ushort(l0)),
                                                  "h"((unsigned short)__bfloat16_as_ushort(l1)));
        int ksg = kq >> 3;
        int tg  = kq & 3;
        int reg = (kq >> 2) & 1;
        int nt  = c >> 3, g = c & 7;
        int lane = g * 4 + tg;
        bfb[((((uint32_t)(l * 2 + 0) * 64 + ksg) * 2 + nt) * 32 + lane) * 2 + reg] = hip;
        bfb[((((uint32_t)(l * 2 + 1) * 64 + ksg) * 2 + nt) * 32 + lane) * 2 + reg] = lop;
    }
    // bayes params
    #pragma unroll
    for (int r = 0; r < 2; r++) {
        int idx = tid * 8 + r * 4;
        int jl = idx >> 9, k = idx & 511;
        float4 m = __ldg((const float4*)(w_mu + (size_t)(j0 + jl) * H + k));
        float4 l4 = __ldg((const float4*)(w_lv + (size_t)(j0 + jl) * H + k));
        float4 s;
        s.x = expf(0.5f * l4.x); s.y = expf(0.5f * l4.y);
        s.z = expf(0.5f * l4.z); s.w = expf(0.5f * l4.w);
        *(float4*)(mu_s + idx) = m;
        *(float4*)(sig_s + idx) = s;
    }
    if (tid < 16) {
        int r = (tid >> 2) * H + u0 + (tid & 3);
        bsum0[tid] = b_ih0[r] + b_hh0[r];
        bsum1[tid] = b_ih1[r] + b_hh1[r];
    }
    if (tid < 4) {
        bmu_s[tid] = b_mu[j0 + tid];
        bsg_s[tid] = expf(0.5f * b_lv[j0 + tid]);
    }
    // state init: split h slices to global; c in per-thread registers; x = 0
    float c0r, c1r;
    {
        int b = tid >> 2, uu = tid & 3;
        int idx = b * H + u0 + uu;
        c0r = init_c[idx];
        c1r = init_c[BH + idx];
        split_store(init_h[idx],      &g_h0hi[0][idx], &g_h0lo[0][idx]);
        split_store(init_h[BH + idx], &g_h1hi[0][idx], &g_h1lo[0][idx]);
        g_xhi[blockIdx.x * NTHR + tid] = __float2bfloat16(0.0f);
        g_xlo[blockIdx.x * NTHR + tid] = __float2bfloat16(0.0f);
    }
    unsigned tgt = NBLK;
    grid_bar(tgt);

    // ---- time loop ----
    for (int t = 0; t < T; t++) {
        const int ping = t & 1, pong = ping ^ 1;

        // Phase A: layer 0
        lstm_phase_mma(smem, 0, g_xhi, g_xlo, g_h0hi[ping], g_h0lo[ping],
                       bsum0, c0r, g_h0hi[pong], g_h0lo[pong], (float*)0, u0);
        tgt += NBLK; grid_bar(tgt);

        // eps prefetch for phase C (latency hidden behind B)
        float4 er[2]; float ebr = 0.0f;
        {
            const float* ew = eps_w + (size_t)t * H * H;
            #pragma unroll
            for (int r = 0; r < 2; r++) {
                int idx = tid * 8 + r * 4;
                int jl = idx >> 9, k = idx & 511;
                er[r] = __ldcs((const float4*)(ew + (size_t)(j0 + jl) * H + k));
            }
            if (tid < 4) ebr = __ldcs(eps_b + (size_t)t * H + j0 + tid);
        }

        // Phase B: layer 1 (writes fp32 timestep output)
        float* out_t = out + (size_t)t * BH;
        lstm_phase_mma(smem, 1, g_h0hi[pong], g_h0lo[pong], g_h1hi[ping], g_h1lo[ping],
                       bsum1, c1r, g_h1hi[pong], g_h1lo[pong], out_t, u0);
        tgt += NBLK; grid_bar(tgt);

        // Phase C: bayes x_next = h1 @ (mu + sig*eps)^T + b_t  (FFMA2, fp32)
        {
            #pragma unroll
            for (int r = 0; r < 2; r++) {
                int idx = tid * 8 + r * 4;
                float4 m = *(const float4*)(mu_s + idx);
                float4 s = *(const float4*)(sig_s + idx);
                float4 e = er[r];
                float4 w;
                w.x = m.x + s.x * e.x; w.y = m.y + s.y * e.y;
                w.z = m.z + s.z * e.z; w.w = m.w + s.w * e.w;
                *(float4*)(Wb + idx) = w;
            }
            if (tid < 4) bb[tid] = bmu_s[tid] + bsg_s[tid] * ebr;

            const int kl = tid & 31;
            const int b0 = (tid >> 5) * 8;
            unsigned long long acc[8][4];
            #pragma unroll
            for (int i = 0; i < 8; i++)
                #pragma unroll
                for (int j = 0; j < 4; j++) acc[i][j] = 0ull;

            for (int ch = 0; ch < 4; ch++) {
                __syncthreads();
                #pragma unroll
                for (int j = 0; j < 8; j++) {
                    int fi = tid + j * NTHR;
                    int b = fi >> 5, kq = fi & 31;
                    *(float4*)(Hs + b * 128 + kq * 4) =
                        __ldcg((const float4*)(out_t + b * H + ch * 128 + kq * 4));
                }
                __syncthreads();
                ulonglong2 hv[8];
                #pragma unroll
                for (int i = 0; i < 8; i++)
                    hv[i] = *(const ulonglong2*)(Hs + (b0 + i) * 128 + kl * 4);
                #pragma unroll
                for (int j = 0; j < 4; j++) {
                    ulonglong2 wv = *(const ulonglong2*)(Wb + j * H + ch * 128 + kl * 4);
                    #pragma unroll
                    for (int i = 0; i < 8; i++) {
                        FMA2(acc[i][j], hv[i].x, wv.x);
                        FMA2(acc[i][j], hv[i].y, wv.y);
                    }
                }
            }
            #pragma unroll
            for (int i = 0; i < 8; i++)
                #pragma unroll
                for (int j = 0; j < 4; j++) {
                    unsigned long long v = acc[i][j], o;
                    o = __shfl_down_sync(0xffffffffu, v, 16); ADD2(v, o);
                    o = __shfl_down_sync(0xffffffffu, v, 8);  ADD2(v, o);
                    o = __shfl_down_sync(0xffffffffu, v, 4);  ADD2(v, o);
                    o = __shfl_down_sync(0xffffffffu, v, 2);  ADD2(v, o);
                    o = __shfl_down_sync(0xffffffffu, v, 1);  ADD2(v, o);
                    if (kl == 0) {
                        float lo, hi; unpack2(v, lo, hi);
                        float xv = lo + hi + bb[j];
                        int idx = (b0 + i) * H + j0 + j;
                        split_store(xv, g_xhi + idx, g_xlo + idx);
                    }
                }
        }
        tgt += NBLK; grid_bar(tgt);
    }
}

// ---------------- launcher ----------------
extern "C" void kernel_launch(void* const* d_in, const int* in_sizes, int n_in,
                              void* d_out, int out_size) {
    const float* init_h = (const float*)d_in[1];
    const float* init_c = (const float*)d_in[2];
    const float* eps_w  = (const float*)d_in[3];
    const float* eps_b  = (const float*)d_in[4];
    const float* W_ih0  = (const float*)d_in[5];
    const float* W_hh0  = (const float*)d_in[6];
    const float* b_ih0  = (const float*)d_in[7];
    const float* b_hh0  = (const float*)d_in[8];
    const float* W_ih1  = (const float*)d_in[9];
    const float* W_hh1  = (const float*)d_in[10];
    const float* b_ih1  = (const float*)d_in[11];
    const float* b_hh1  = (const float*)d_in[12];
    const float* w_mu   = (const float*)d_in[13];
    const float* w_lv   = (const float*)d_in[14];
    const float* b_mu   = (const float*)d_in[15];
    const float* b_lv   = (const float*)d_in[16];
    float* out = (float*)d_out;

    cudaFuncSetAttribute((const void*)dlstm_persistent,
                         cudaFuncAttributeMaxDynamicSharedMemorySize, SMEM_BYTES);

    reset_kernel<<<1, 1>>>();
    dlstm_persistent<<<NBLK, NTHR, SMEM_BYTES>>>(
        init_h, init_c, eps_w, eps_b,
        W_ih0, W_hh0, b_ih0, b_hh0,
        W_ih1, W_hh1, b_ih1, b_hh1,
        w_mu, w_lv, b_mu, b_lv, out);
}

// round 13
// speedup vs baseline: 1.9774x; 1.9774x over previous
#include <cuda_runtime.h>
#include <cuda_bf16.h>
#include <math.h>
#include <stdint.h>

// Shapes fixed by the dataset
#define H    512
#define Bm   64
#define T    256
#define BH   (Bm * H)
#define NBLK 128          // persistent blocks, 1/SM
#define NTHR 256
#define NK   32           // ksteps (of 16) per 512-wide activation buffer

// ---- SMEM byte offsets ----
// Bfrag: weight fragments [layer2][pass2][ks64][nt2][lane32][reg2] b32 = 128KB
#define OFF_BF   0
#define OFF_CP   131072      // Cp [w8][b64][n16] f32 = 32KB (cross-warp reduction)
#define OFF_MU   163840      // [4][512] f32 bayes mu rows (8KB)
#define OFF_SIG  172032      // (8KB)
#define OFF_WB   180224      // (8KB)
#define OFF_BS0  188416      // [16] f32
#define OFF_BS1  188480
#define OFF_BMU  188544
#define OFF_BSG  188560
#define OFF_BB   188576
#define SMEM_BYTES 188672

// ---- persistent device state (no allocations allowed) ----
// Activation buffers in MMA-fragment order:
//   index = (((pass*NK + ks)*4 + mt)*32 + lane)*4 + reg   (b32 units)
//   reg0: rows(b&8==0) k-lo | reg1: rows(b&8) k-lo | reg2/3: same, k-hi
//   lane = 4*(b&7) + t, b32 at (ks,t) holds cols (16ks+2t, 16ks+2t+1)
// pass0 = bf16 hi, pass1 = bf16 lo. Buffer = 32768 b32 = 128KB.
#define AF_PASS_STRIDE 16384
__device__ unsigned g_bar;
__device__ volatile unsigned g_dead;   // watchdog
__device__ __align__(16) uint32_t g_Xf[2 * AF_PASS_STRIDE];
__device__ __align__(16) uint32_t g_H0f[2][2 * AF_PASS_STRIDE];
__device__ __align__(16) uint32_t g_H1f[2][2 * AF_PASS_STRIDE];

__device__ __forceinline__ uint32_t afg_idx(int pass, int ks, int mt, int lane) {
    return (((uint32_t)(pass * NK + ks) * 4 + mt) * 32 + (uint32_t)lane) * 4;
}

// m16n8k16 bf16 mma, fp32 accumulate (sm_80+ baseline — OK on plain sm_100)
#define MMA16816(c, a, b)                                                        \
    asm volatile("mma.sync.aligned.m16n8k16.row.col.f32.bf16.bf16.f32 "          \
        "{%0,%1,%2,%3}, {%4,%5,%6,%7}, {%8,%9}, {%0,%1,%2,%3};"                  \
        : "+f"((c)[0]), "+f"((c)[1]), "+f"((c)[2]), "+f"((c)[3])                 \
        : "r"((a)[0]), "r"((a)[1]), "r"((a)[2]), "r"((a)[3]),                    \
          "r"((b)[0]), "r"((b)[1]))

// Packed fp32x2 ops for the bayes phase
#define FMA2(d, a, b) asm("fma.rn.f32x2 %0, %1, %2, %0;" : "+l"(d) : "l"(a), "l"(b))
#define ADD2(d, a)    asm("add.rn.f32x2 %0, %0, %1;"     : "+l"(d) : "l"(a))
__device__ __forceinline__ void unpack2(unsigned long long v, float& lo, float& hi) {
    asm("mov.b64 {%0, %1}, %2;" : "=f"(lo), "=f"(hi) : "l"(v));
}

__global__ void reset_kernel() { g_bar = 0u; g_dead = 0u; }

// Bounded grid barrier: tight L2 spin; watchdog turns any wedge into fast
// termination instead of a container-killing hang.
__device__ __forceinline__ void grid_bar(unsigned target) {
    __syncthreads();
    if (threadIdx.x == 0) {
        __threadfence();
        atomicAdd(&g_bar, 1u);
        unsigned spin = 0;
        while (!g_dead) {
            unsigned v;
            asm volatile("ld.global.cg.u32 %0, [%1];" : "=r"(v) : "l"(&g_bar));
            if (v >= target) break;
            if (++spin > 100000000u) { g_dead = 1u; break; }
        }
        __threadfence();
    }
    __syncthreads();
}

__device__ __forceinline__ void split_bf16(float v, uint32_t& hu, uint32_t& lu) {
    __nv_bfloat16 hb = __float2bfloat16(v);
    __nv_bfloat16 lb = __float2bfloat16(v - __bfloat162float(hb));
    hu = (uint32_t)__bfloat16_as_ushort(hb);
    lu = (uint32_t)__bfloat16_as_ushort(lb);
}

// Pair-packed fragment write for thread (b, uu) (uu = unit 0..3 of block bk).
// Threads uu and uu+1 are adjacent lanes; even-uu threads pack & write.
__device__ __forceinline__ void frag_write_pair(
    uint32_t* __restrict__ buf, int bk, int b, int uu, float hval)
{
    uint32_t hu, lu;
    split_bf16(hval, hu, lu);
    uint32_t hn2 = __shfl_down_sync(0xffffffffu, hu, 1);
    uint32_t ln2 = __shfl_down_sync(0xffffffffu, lu, 1);
    if ((uu & 1) == 0) {
        uint32_t hp = hu | (hn2 << 16);
        uint32_t lp = lu | (ln2 << 16);
        int ks  = bk >> 2;
        int mt  = b >> 4;
        int reg = ((b >> 3) & 1) + ((bk & 2) ? 2 : 0);
        int lane_t = 4 * (b & 7) + (bk & 1) * 2 + (uu >> 1);
        uint32_t idx = afg_idx(0, ks, mt, lane_t) + (uint32_t)reg;
        buf[idx] = hp;
        buf[idx + AF_PASS_STRIDE] = lp;
    }
}

// ---- one LSTM layer phase: direct-fragment loads, zero staging ----
// gates C[64][16] = [x | hprev] @ W^T, K=1024 = 64 ksteps; warp w owns
// ksteps {w, w+8, ..., w+56}. 3-pass bf16 hi/lo split.
__device__ __forceinline__ void lstm_phase_frag(
    char* smem, int layer,
    const uint32_t* __restrict__ xf, const uint32_t* __restrict__ hf,
    const float* __restrict__ bsum, float& cr,
    uint32_t* __restrict__ hnf, float* __restrict__ out_t,
    int bk, int u0)
{
    const int tid  = threadIdx.x;
    const int w    = tid >> 5;
    const int lane = tid & 31;
    const uint32_t* bfb = (const uint32_t*)(smem + OFF_BF);

    float acc[4][2][4];
    #pragma unroll
    for (int mt = 0; mt < 4; mt++)
        #pragma unroll
        for (int nt = 0; nt < 2; nt++)
            #pragma unroll
            for (int r = 0; r < 4; r++) acc[mt][nt][r] = 0.0f;

    // prefetch kstep ck=0 (ksg = w < 32 -> x buffer)
    uint4 curh[4], curl[4];
    #pragma unroll
    for (int mt = 0; mt < 4; mt++) {
        curh[mt] = __ldcg((const uint4*)(xf + afg_idx(0, w, mt, lane)));
        curl[mt] = __ldcg((const uint4*)(xf + afg_idx(1, w, mt, lane)));
    }

    #pragma unroll
    for (int ck = 0; ck < 8; ck++) {
        const int ksg = ck * 8 + w;
        uint4 nxth[4], nxtl[4];
        if (ck < 7) {
            int nks = ksg + 8;
            const uint32_t* s = (nks < NK) ? xf : hf;
            int ksl = nks & (NK - 1);
            #pragma unroll
            for (int mt = 0; mt < 4; mt++) {
                nxth[mt] = __ldcg((const uint4*)(s + afg_idx(0, ksl, mt, lane)));
                nxtl[mt] = __ldcg((const uint4*)(s + afg_idx(1, ksl, mt, lane)));
            }
        }
        // B fragments (SMEM-resident, layout validated in R10/R12)
        uint32_t Bh[2][2], Bl[2][2];
        #pragma unroll
        for (int nt = 0; nt < 2; nt++) {
            uint32_t ih = ((((uint32_t)(layer * 2 + 0) * 64 + ksg) * 2 + nt) * 32 + lane) * 2;
            uint32_t il = ((((uint32_t)(layer * 2 + 1) * 64 + ksg) * 2 + nt) * 32 + lane) * 2;
            uint2 vh = *(const uint2*)(bfb + ih);
            uint2 vl = *(const uint2*)(bfb + il);
            Bh[nt][0] = vh.x; Bh[nt][1] = vh.y;
            Bl[nt][0] = vl.x; Bl[nt][1] = vl.y;
        }
        #pragma unroll
        for (int mt = 0; mt < 4; mt++)
            #pragma unroll
            for (int nt = 0; nt < 2; nt++) {
                MMA16816(acc[mt][nt], ((const uint32_t*)&curh[mt]), Bh[nt]);
                MMA16816(acc[mt][nt], ((const uint32_t*)&curh[mt]), Bl[nt]);
                MMA16816(acc[mt][nt], ((const uint32_t*)&curl[mt]), Bh[nt]);
            }
        if (ck < 7) {
            #pragma unroll
            for (int mt = 0; mt < 4; mt++) { curh[mt] = nxth[mt]; curl[mt] = nxtl[mt]; }
        }
    }

    // cross-warp K reduction via SMEM partials (per-warp exclusive region)
    float* cp = (float*)(smem + OFF_CP);  // Cp[w][64][16]
    {
        int g = lane >> 2, tg = lane & 3;
        #pragma unroll
        for (int mt = 0; mt < 4; mt++)
            #pragma unroll
            for (int nt = 0; nt < 2; nt++) {
                int n0 = nt * 8 + tg * 2;
                int row = w * 64 + mt * 16 + g;
                *(float2*)(cp + row * 16 + n0) =
                    make_float2(acc[mt][nt][0], acc[mt][nt][1]);
                *(float2*)(cp + (row + 8) * 16 + n0) =
                    make_float2(acc[mt][nt][2], acc[mt][nt][3]);
            }
    }
    __syncthreads();

    // cell update: thread -> (batch, unit); c in register all sequence
    {
        int b = tid >> 2, uu = tid & 3;
        float gsum[4];
        #pragma unroll
        for (int gate = 0; gate < 4; gate++) {
            int n = gate * 4 + uu;
            float s = 0.0f;
            #pragma unroll
            for (int ww = 0; ww < 8; ww++) s += cp[(ww * 64 + b) * 16 + n];
            gsum[gate] = s + bsum[n];
        }
        float iv = 1.0f / (1.0f + expf(-gsum[0]));
        float fv = 1.0f / (1.0f + expf(-gsum[1]));
        float gv = tanhf(gsum[2]);
        float ov = 1.0f / (1.0f + expf(-gsum[3]));
        float cn = fv * cr + iv * gv;
        cr = cn;
        float hn = ov * tanhf(cn);
        if (out_t) out_t[(size_t)b * H + u0 + uu] = hn;
        frag_write_pair(hnf, bk, b, uu, hn);
    }
}

extern "C" __global__ void __launch_bounds__(NTHR, 1)
dlstm_persistent(const float* __restrict__ init_h, const float* __restrict__ init_c,
                 const float* __restrict__ eps_w,  const float* __restrict__ eps_b,
                 const float* __restrict__ W_ih0, const float* __restrict__ W_hh0,
                 const float* __restrict__ b_ih0, const float* __restrict__ b_hh0,
                 const float* __restrict__ W_ih1, const float* __restrict__ W_hh1,
                 const float* __restrict__ b_ih1, const float* __restrict__ b_hh1,
                 const float* __restrict__ w_mu,  const float* __restrict__ w_lv,
                 const float* __restrict__ b_mu,  const float* __restrict__ b_lv,
                 float* __restrict__ out)
{
    extern __shared__ __align__(16) char smem[];
    const int tid = threadIdx.x;
    const int bk = blockIdx.x;
    const int u0 = bk * 4, j0 = u0;

    uint32_t* bfb  = (uint32_t*)(smem + OFF_BF);
    float* mu_s  = (float*)(smem + OFF_MU);
    float* sig_s = (float*)(smem + OFF_SIG);
    float* Wb    = (float*)(smem + OFF_WB);
    float* bsum0 = (float*)(smem + OFF_BS0);
    float* bsum1 = (float*)(smem + OFF_BS1);
    float* bmu_s = (float*)(smem + OFF_BMU);
    float* bsg_s = (float*)(smem + OFF_BSG);
    float* bb    = (float*)(smem + OFF_BB);

    // ---- prologue: weight fragments (resident whole run; layout validated) ----
    for (int idx = tid; idx < 2 * 16 * 512; idx += NTHR) {
        int l  = idx >> 13;
        int c  = (idx >> 9) & 15;
        int kq = idx & 511;
        int k  = kq * 2;
        int r  = (c >> 2) * H + u0 + (c & 3);
        const float* Wih = l ? W_ih1 : W_ih0;
        const float* Whh = l ? W_hh1 : W_hh0;
        const float* src = (k < H) ? (Wih + (size_t)r * H + k)
                                   : (Whh + (size_t)r * H + (k - H));
        float2 wv = *(const float2*)src;
        uint32_t h0u, l0u, h1u, l1u;
        split_bf16(wv.x, h0u, l0u);
        split_bf16(wv.y, h1u, l1u);
        uint32_t hip = h0u | (h1u << 16);
        uint32_t lop = l0u | (l1u << 16);
        int ksg = kq >> 3;
        int tg  = kq & 3;
        int reg = (kq >> 2) & 1;
        int nt  = c >> 3, g = c & 7;
        int lane = g * 4 + tg;
        bfb[((((uint32_t)(l * 2 + 0) * 64 + ksg) * 2 + nt) * 32 + lane) * 2 + reg] = hip;
        bfb[((((uint32_t)(l * 2 + 1) * 64 + ksg) * 2 + nt) * 32 + lane) * 2 + reg] = lop;
    }
    // bayes params
    #pragma unroll
    for (int r = 0; r < 2; r++) {
        int idx = tid * 8 + r * 4;
        int jl = idx >> 9, k = idx & 511;
        float4 m = __ldg((const float4*)(w_mu + (size_t)(j0 + jl) * H + k));
        float4 l4 = __ldg((const float4*)(w_lv + (size_t)(j0 + jl) * H + k));
        float4 s;
        s.x = expf(0.5f * l4.x); s.y = expf(0.5f * l4.y);
        s.z = expf(0.5f * l4.z); s.w = expf(0.5f * l4.w);
        *(float4*)(mu_s + idx) = m;
        *(float4*)(sig_s + idx) = s;
    }
    if (tid < 16) {
        int r = (tid >> 2) * H + u0 + (tid & 3);
        bsum0[tid] = b_ih0[r] + b_hh0[r];
        bsum1[tid] = b_ih1[r] + b_hh1[r];
    }
    if (tid < 4) {
        bmu_s[tid] = b_mu[j0 + tid];
        bsg_s[tid] = expf(0.5f * b_lv[j0 + tid]);
    }
    // state init: fragments of h0/h1/x slices; c in per-thread registers
    float c0r, c1r;
    {
        int b = tid >> 2, uu = tid & 3;
        int idx = b * H + u0 + uu;
        c0r = init_c[idx];
        c1r = init_c[BH + idx];
        frag_write_pair(g_H0f[0], bk, b, uu, init_h[idx]);
        frag_write_pair(g_H1f[0], bk, b, uu, init_h[BH + idx]);
        frag_write_pair(g_Xf,     bk, b, uu, 0.0f);
    }
    unsigned tgt = NBLK;
    grid_bar(tgt);

    // ---- time loop ----
    for (int t = 0; t < T; t++) {
        const int ping = t & 1, pong = ping ^ 1;

        // Phase A: layer 0  (x-part = Xf, h-part = H0f[ping])
        lstm_phase_frag(smem, 0, g_Xf, g_H0f[ping], bsum0, c0r,
                        g_H0f[pong], (float*)0, bk, u0);
        tgt += NBLK; grid_bar(tgt);

        // eps prefetch for phase C (latency hidden behind B)
        float4 er[2]; float ebr = 0.0f;
        {
            const float* ew = eps_w + (size_t)t * H * H;
            #pragma unroll
            for (int r = 0; r < 2; r++) {
                int idx = tid * 8 + r * 4;
                int jl = idx >> 9, k = idx & 511;
                er[r] = __ldcs((const float4*)(ew + (size_t)(j0 + jl) * H + k));
            }
            if (tid < 4) ebr = __ldcs(eps_b + (size_t)t * H + j0 + tid);
        }

        // Phase B: layer 1 (x-part = H0f[pong] just written; writes out_t)
        float* out_t = out + (size_t)t * BH;
        lstm_phase_frag(smem, 1, g_H0f[pong], g_H1f[ping], bsum1, c1r,
                        g_H1f[pong], out_t, bk, u0);
        tgt += NBLK; grid_bar(tgt);

        // Phase C: bayes x_next = h1 @ (mu + sig*eps)^T + b_t  (FFMA2, fp32)
        // Warps own disjoint batch rows -> direct ldcg, no staging, no syncs.
        {
            #pragma unroll
            for (int r = 0; r < 2; r++) {
                int idx = tid * 8 + r * 4;
                float4 m = *(const float4*)(mu_s + idx);
                float4 s = *(const float4*)(sig_s + idx);
                float4 e = er[r];
                float4 wv;
                wv.x = m.x + s.x * e.x; wv.y = m.y + s.y * e.y;
                wv.z = m.z + s.z * e.z; wv.w = m.w + s.w * e.w;
                *(float4*)(Wb + idx) = wv;
            }
            if (tid < 4) bb[tid] = bmu_s[tid] + bsg_s[tid] * ebr;
            __syncthreads();

            const int kl = tid & 31;
            const int b0 = (tid >> 5) * 8;
            unsigned long long acc[8][4];
            #pragma unroll
            for (int i = 0; i < 8; i++)
                #pragma unroll
                for (int j = 0; j < 4; j++) acc[i][j] = 0ull;

            #pragma unroll
            for (int ch = 0; ch < 4; ch++) {
                ulonglong2 hv[8];
                #pragma unroll
                for (int i = 0; i < 8; i++)
                    hv[i] = __ldcg((const ulonglong2*)(out_t + (size_t)(b0 + i) * H
                                                      + ch * 128 + kl * 4));
                #pragma unroll
                for (int j = 0; j < 4; j++) {
                    ulonglong2 wv = *(const ulonglong2*)(Wb + j * H + ch * 128 + kl * 4);
                    #pragma unroll
                    for (int i = 0; i < 8; i++) {
                        FMA2(acc[i][j], hv[i].x, wv.x);
                        FMA2(acc[i][j], hv[i].y, wv.y);
                    }
                }
            }
            float xres[8][4];
            #pragma unroll
            for (int i = 0; i < 8; i++)
                #pragma unroll
                for (int j = 0; j < 4; j++) {
                    unsigned long long v = acc[i][j], o;
                    o = __shfl_down_sync(0xffffffffu, v, 16); ADD2(v, o);
                    o = __shfl_down_sync(0xffffffffu, v, 8);  ADD2(v, o);
                    o = __shfl_down_sync(0xffffffffu, v, 4);  ADD2(v, o);
                    o = __shfl_down_sync(0xffffffffu, v, 2);  ADD2(v, o);
                    o = __shfl_down_sync(0xffffffffu, v, 1);  ADD2(v, o);
                    float lo, hi; unpack2(v, lo, hi);
                    xres[i][j] = lo + hi + bb[j];
                }
            // fragment write of x_next (lane 0 of each warp holds the sums)
            if (kl == 0) {
                int ks = bk >> 2;
                #pragma unroll
                for (int i = 0; i < 8; i++) {
                    int b = b0 + i;
                    int mt = b >> 4;
                    int reg = ((b >> 3) & 1) + ((bk & 2) ? 2 : 0);
                    #pragma unroll
                    for (int jh = 0; jh < 2; jh++) {
                        uint32_t h0u, l0u, h1u, l1u;
                        split_bf16(xres[i][2 * jh],     h0u, l0u);
                        split_bf16(xres[i][2 * jh + 1], h1u, l1u);
                        uint32_t hp = h0u | (h1u << 16);
                        uint32_t lp = l0u | (l1u << 16);
                        int lane_t = 4 * (b & 7) + (bk & 1) * 2 + jh;
                        uint32_t idx = afg_idx(0, ks, mt, lane_t) + (uint32_t)reg;
                        g_Xf[idx] = hp;
                        g_Xf[idx + AF_PASS_STRIDE] = lp;
                    }
                }
            }
        }
        tgt += NBLK; grid_bar(tgt);
    }
}

// ---------------- launcher ----------------
extern "C" void kernel_launch(void* const* d_in, const int* in_sizes, int n_in,
                              void* d_out, int out_size) {
    const float* init_h = (const float*)d_in[1];
    const float* init_c = (const float*)d_in[2];
    const float* eps_w  = (const float*)d_in[3];
    const float* eps_b  = (const float*)d_in[4];
    const float* W_ih0  = (const float*)d_in[5];
    const float* W_hh0  = (const float*)d_in[6];
    const float* b_ih0  = (const float*)d_in[7];
    const float* b_hh0  = (const float*)d_in[8];
    const float* W_ih1  = (const float*)d_in[9];
    const float* W_hh1  = (const float*)d_in[10];
    const float* b_ih1  = (const float*)d_in[11];
    const float* b_hh1  = (const float*)d_in[12];
    const float* w_mu   = (const float*)d_in[13];
    const float* w_lv   = (const float*)d_in[14];
    const float* b_mu   = (const float*)d_in[15];
    const float* b_lv   = (const float*)d_in[16];
    float* out = (float*)d_out;

    cudaFuncSetAttribute((const void*)dlstm_persistent,
                         cudaFuncAttributeMaxDynamicSharedMemorySize, SMEM_BYTES);

    reset_kernel<<<1, 1>>>();
    dlstm_persistent<<<NBLK, NTHR, SMEM_BYTES>>>(
        init_h, init_c, eps_w, eps_b,
        W_ih0, W_hh0, b_ih0, b_hh0,
        W_ih1, W_hh1, b_ih1, b_hh1,
        w_mu, w_lv, b_mu, b_lv, out);
}